// round 11
// baseline (speedup 1.0000x reference)
#include <cuda_runtime.h>
#include <cuda_fp16.h>
#include <cstdint>

#define DI __device__ __forceinline__

// ---------------- problem constants ----------------
constexpr int TOKENS = 4 * 2048;        // 8192
constexpr int DDIM   = 1024;
constexpr int FDIM   = 2048;
constexpr int EEXP   = 8;
constexpr int NA     = TOKENS * 2;      // 16384 assignments (K=2)
constexpr int CAP    = 2560;            // ceil(1.25 * 16384 / 8)

// ---------------- scratch (device globals; no runtime alloc) ----------------
__device__ __half g_Hh[(size_t)EEXP * CAP * FDIM];    // 80 MB (fp16 H)
__device__ float  g_Y [(size_t)EEXP * CAP * DDIM];    // 80 MB
__device__ __half g_xh [(size_t)TOKENS * DDIM];       // 16 MB
__device__ __half g_w1h[(size_t)EEXP * FDIM * DDIM];  // 32 MB
__device__ __half g_w3h[(size_t)EEXP * FDIM * DDIM];  // 32 MB
__device__ __half g_w2h[(size_t)EEXP * DDIM * FDIM];  // 32 MB
__device__ int   g_slot_token[EEXP * CAP];
__device__ int   g_count[EEXP];
__device__ int   g_assign_e[NA];
__device__ int   g_assign_pos[NA];
__device__ float g_assign_gate[NA];
__device__ float g_block_imp[(TOKENS / 8) * EEXP];
__device__ float g_aux;

// ---------------- helpers ----------------
DI uint32_t smem_u32(const void* p) {
    uint32_t a;
    asm("{ .reg .u64 t; cvta.to.shared.u64 t, %1; cvt.u32.u64 %0, t; }" : "=r"(a) : "l"(p));
    return a;
}
DI void cp16(uint32_t dst, const void* src, uint32_t valid) {
    asm volatile("cp.async.cg.shared.global [%0], [%1], 16, %2;"
                 :: "r"(dst), "l"(src), "r"(valid) : "memory");
}
DI void cp_commit() { asm volatile("cp.async.commit_group;" ::: "memory"); }
template <int N> DI void cp_wait() { asm volatile("cp.async.wait_group %0;" :: "n"(N) : "memory"); }

DI void ldsm4(uint32_t r[4], uint32_t addr) {
    asm volatile("ldmatrix.sync.aligned.m8n8.x4.shared.b16 {%0,%1,%2,%3}, [%4];"
                 : "=r"(r[0]), "=r"(r[1]), "=r"(r[2]), "=r"(r[3]) : "r"(addr));
}
// m16n8k16 fp16 mma, fp32 accum (portable sm_80+)
DI void mma16(float c[4], const uint32_t a[4], const uint32_t b0, const uint32_t b1) {
    asm volatile("mma.sync.aligned.m16n8k16.row.col.f32.f16.f16.f32 "
                 "{%0,%1,%2,%3}, {%4,%5,%6,%7}, {%8,%9}, {%0,%1,%2,%3};"
                 : "+f"(c[0]), "+f"(c[1]), "+f"(c[2]), "+f"(c[3])
                 : "r"(a[0]), "r"(a[1]), "r"(a[2]), "r"(a[3]), "r"(b0), "r"(b1));
}
DI float silu(float a) { return a / (1.f + __expf(-a)); }

// ---------------- GEMM tiling ----------------
// 512 threads/CTA, warp grid 4x4, warp tile 32x32 -> ~120 regs/thread, 16 warps/SM
constexpr int BM = 128, BN = 128, BK = 32, STAGES = 4;
constexpr int RHB = 80;                       // padded row stride in bytes (32 halves + 8 pad)
constexpr int TB  = 128 * RHB;                // 10240 B per stage tile
constexpr uint32_t SMEM1 = 3 * STAGES * TB;   // A,B1,B3 : 122880 B
constexpr uint32_t SMEM2 = 2 * STAGES * TB;   // A,B     :  81920 B

// ---------------- fused fp32 -> fp16(RN) conversion of w1, w3, w2 -----------
__global__ void tohalf3_kernel(const float* __restrict__ s1, __half* __restrict__ d1,
                               const float* __restrict__ s2, __half* __restrict__ d2,
                               const float* __restrict__ s3, __half* __restrict__ d3,
                               int n4each) {
    int i = blockIdx.x * blockDim.x + threadIdx.x;
    int stride = gridDim.x * blockDim.x;
    for (int idx = i; idx < 3 * n4each; idx += stride) {
        int seg = idx / n4each, off = idx - seg * n4each;
        const float4* src = reinterpret_cast<const float4*>(seg == 0 ? s1 : (seg == 1 ? s2 : s3));
        uint2* dst = reinterpret_cast<uint2*>(seg == 0 ? d1 : (seg == 1 ? d2 : d3));
        float4 v = src[off];
        __half2 h01 = __floats2half2_rn(v.x, v.y);
        __half2 h23 = __floats2half2_rn(v.z, v.w);
        uint2 pk;
        pk.x = *reinterpret_cast<uint32_t*>(&h01);
        pk.y = *reinterpret_cast<uint32_t*>(&h23);
        dst[off] = pk;
    }
}

// ---------------- router (also emits xh = fp16(x)) ----------------
__global__ __launch_bounds__(256) void router_kernel(
    const float* __restrict__ x, const float* __restrict__ rw, const float* __restrict__ rb,
    __half* __restrict__ xh) {
    __shared__ float s_w[EEXP * DDIM];
    __shared__ float s_b[EEXP];
    __shared__ float s_probs[8][EEXP];
    int tid = threadIdx.x;
    for (int i = tid; i < EEXP * DDIM / 4; i += 256)
        reinterpret_cast<float4*>(s_w)[i] = reinterpret_cast<const float4*>(rw)[i];
    if (tid < EEXP) s_b[tid] = rb[tid];
    __syncthreads();

    int warp = tid >> 5, lane = tid & 31;
    int token = blockIdx.x * 8 + warp;
    const float4* xr = reinterpret_cast<const float4*>(x + (size_t)token * DDIM);
    uint2* xhw = reinterpret_cast<uint2*>(xh + (size_t)token * DDIM);

    float p[EEXP];
#pragma unroll
    for (int e = 0; e < EEXP; ++e) p[e] = 0.f;
#pragma unroll
    for (int j = 0; j < 8; ++j) {
        float4 v = xr[lane + j * 32];
        int base = (lane + j * 32) * 4;
#pragma unroll
        for (int e = 0; e < EEXP; ++e) {
            const float* wr = s_w + e * DDIM + base;
            p[e] += v.x * wr[0] + v.y * wr[1] + v.z * wr[2] + v.w * wr[3];
        }
        __half2 h01 = __floats2half2_rn(v.x, v.y);
        __half2 h23 = __floats2half2_rn(v.z, v.w);
        uint2 pk;
        pk.x = *reinterpret_cast<uint32_t*>(&h01);
        pk.y = *reinterpret_cast<uint32_t*>(&h23);
        xhw[lane + j * 32] = pk;
    }
#pragma unroll
    for (int off = 16; off > 0; off >>= 1)
#pragma unroll
        for (int e = 0; e < EEXP; ++e) p[e] += __shfl_xor_sync(0xffffffffu, p[e], off);

    if (lane == 0) {
        float pr[EEXP];
        float mx = -1e30f;
#pragma unroll
        for (int e = 0; e < EEXP; ++e) { p[e] += s_b[e]; mx = fmaxf(mx, p[e]); }
        float sum = 0.f;
#pragma unroll
        for (int e = 0; e < EEXP; ++e) { pr[e] = expf(p[e] - mx); sum += pr[e]; }
        float inv = 1.f / sum;
#pragma unroll
        for (int e = 0; e < EEXP; ++e) pr[e] *= inv;

        int e0 = 0;
#pragma unroll
        for (int e = 1; e < EEXP; ++e) if (pr[e] > pr[e0]) e0 = e;
        int e1 = (e0 == 0) ? 1 : 0;
#pragma unroll
        for (int e = 0; e < EEXP; ++e) if (e != e0 && pr[e] > pr[e1]) e1 = e;

        float s2 = fmaxf(pr[e0] + pr[e1], 1e-9f);
        g_assign_e[2 * token]        = e0;
        g_assign_gate[2 * token]     = pr[e0] / s2;
        g_assign_e[2 * token + 1]    = e1;
        g_assign_gate[2 * token + 1] = pr[e1] / s2;
#pragma unroll
        for (int e = 0; e < EEXP; ++e) s_probs[warp][e] = pr[e];
    }
    __syncthreads();
    if (tid < EEXP) {
        float s = 0.f;
#pragma unroll
        for (int w = 0; w < 8; ++w) s += s_probs[w][tid];
        g_block_imp[blockIdx.x * EEXP + tid] = s;
    }
}

// ---------------- rank: init slots + stable per-expert ranking + aux ---------
__global__ __launch_bounds__(1024) void rank_kernel() {
    __shared__ int warp_off[32][EEXP];
    __shared__ int base[EEXP];
    __shared__ float imp_part[1024];
    __shared__ float prod[EEXP];
    int tid = threadIdx.x, warp = tid >> 5, lane = tid & 31;
    for (int i = tid; i < EEXP * CAP; i += 1024) g_slot_token[i] = -1;
    if (tid < EEXP) base[tid] = 0;
    __syncthreads();

    for (int chunk = 0; chunk < NA / 1024; ++chunk) {
        int a = chunk * 1024 + tid;
        int e = g_assign_e[a];
        unsigned m = __match_any_sync(0xffffffffu, e);
        int rank = __popc(m & ((1u << lane) - 1));
        int cnt  = __popc(m);
        int leader = __ffs(m) - 1;
        if (tid < 256) reinterpret_cast<int*>(warp_off)[tid] = 0;
        __syncthreads();
        if (lane == leader) warp_off[warp][e] = cnt;
        __syncthreads();
        if (tid < EEXP) {
            int run = base[tid];
            for (int w = 0; w < 32; ++w) { int c = warp_off[w][tid]; warp_off[w][tid] = run; run += c; }
            base[tid] = run;
        }
        __syncthreads();
        int pos = warp_off[warp][e] + rank;
        g_assign_pos[a] = pos;
        if (pos < CAP) g_slot_token[e * CAP + pos] = a >> 1;
        __syncthreads();
    }

    float s = 0.f;
    int eidx = tid & 7;
    for (int b = tid >> 3; b < TOKENS / 8; b += 128) s += g_block_imp[b * EEXP + eidx];
    imp_part[tid] = s;
    __syncthreads();
    if (tid < EEXP) {
        float tot = 0.f;
        for (int i = tid; i < 1024; i += 8) tot += imp_part[i];
        float imp = tot / (float)TOKENS;
        float ld  = (float)base[tid] / (float)NA;
        prod[tid] = imp * ld;
        g_count[tid] = base[tid];
    }
    __syncthreads();
    if (tid == 0) {
        float acc = 0.f;
        for (int e = 0; e < EEXP; ++e) acc += prod[e];
        g_aux = 0.01f * (float)EEXP * acc;
    }
}

// ---------------- GEMM1 (fp16): H = silu(Xb@W1^T) * (Xb@W3^T) ----------------
__global__ __launch_bounds__(512, 1) void gemm1_kernel(
    const __half* __restrict__ xh, const __half* __restrict__ w1h, const __half* __restrict__ w3h) {
    const int e = blockIdx.z, m0 = blockIdx.x * BM, n0 = blockIdx.y * BN;
    if (m0 >= g_count[e]) return;           // outputs for these slots are never read

    extern __shared__ __align__(128) char sm[];
    const uint32_t sbase = smem_u32(sm);
    const int tid = threadIdx.x, wid = tid >> 5, lane = tid & 31;
    const int wm = wid >> 2, wn = wid & 3;  // warp grid 4x4 -> warp tile 32x32
    const int grp = lane >> 2, tg = lane & 3;

    // loader: 4 threads per row, 16B each
    const int r = tid >> 2, h = tid & 3;
    const int tok = g_slot_token[e * CAP + m0 + r];
    const __half* asrc = xh + (size_t)(tok < 0 ? 0 : tok) * DDIM + h * 8;
    const uint32_t av = (tok >= 0) ? 16u : 0u;
    const __half* b1src = w1h + ((size_t)e * FDIM + n0 + r) * DDIM + h * 8;
    const __half* b3src = w3h + ((size_t)e * FDIM + n0 + r) * DDIM + h * 8;
    const uint32_t doff = (uint32_t)(r * RHB + h * 16);

    auto load_stage = [&](int s, int k0) {
        uint32_t ad  = sbase + (uint32_t)s * TB + doff;
        uint32_t b1d = ad + STAGES * TB;
        uint32_t b3d = b1d + STAGES * TB;
        cp16(ad,  asrc  + k0, av);
        cp16(b1d, b1src + k0, 16u);
        cp16(b3d, b3src + k0, 16u);
        cp_commit();
    };

    float acc1[2][4][4] = {}, acc3[2][4][4] = {};
    load_stage(0, 0);
    load_stage(1, BK);
    load_stage(2, 2 * BK);

    // ldmatrix lane offsets
    const uint32_t a_lo = (uint32_t)((lane & 15) * RHB + ((lane >> 4) << 4));
    const uint32_t b_lo = (uint32_t)((lane & 7) * RHB + (((lane >> 3) & 1) << 4)
                                     + ((lane >> 4) * 8 * RHB));

    constexpr int KT = DDIM / BK;  // 32
    for (int kt = 0; kt < KT; ++kt) {
        cp_wait<2>();
        __syncthreads();
        if (kt + 3 < KT) load_stage((kt + 3) % STAGES, (kt + 3) * BK);
        const uint32_t A_  = sbase + (uint32_t)(kt % STAGES) * TB;
        const uint32_t B1_ = A_ + STAGES * TB;
        const uint32_t B3_ = B1_ + STAGES * TB;
#pragma unroll
        for (int ks = 0; ks < 2; ++ks) {
            const uint32_t ko = ks * 32;
            uint32_t a[2][4];
#pragma unroll
            for (int mt = 0; mt < 2; ++mt)
                ldsm4(a[mt], A_ + (uint32_t)((wm * 32 + mt * 16) * RHB) + ko + a_lo);
            uint32_t b1f[2][4], b3f[2][4];
#pragma unroll
            for (int np = 0; np < 2; ++np) {
                uint32_t nrow = (uint32_t)((wn * 32 + np * 16) * RHB) + ko + b_lo;
                ldsm4(b1f[np], B1_ + nrow);
                ldsm4(b3f[np], B3_ + nrow);
            }
#pragma unroll
            for (int mt = 0; mt < 2; ++mt)
#pragma unroll
                for (int np = 0; np < 2; ++np) {
                    mma16(acc1[mt][np * 2],     a[mt], b1f[np][0], b1f[np][1]);
                    mma16(acc1[mt][np * 2 + 1], a[mt], b1f[np][2], b1f[np][3]);
                    mma16(acc3[mt][np * 2],     a[mt], b3f[np][0], b3f[np][1]);
                    mma16(acc3[mt][np * 2 + 1], a[mt], b3f[np][2], b3f[np][3]);
                }
        }
    }

    // epilogue: silu(h1)*h3 -> g_Hh (fp16; it is gemm2's A operand)
#pragma unroll
    for (int mt = 0; mt < 2; ++mt) {
        int mg = m0 + wm * 32 + mt * 16 + grp;
        __half* H0 = g_Hh + (size_t)(e * CAP + mg) * FDIM + n0;
        __half* H8 = H0 + 8 * FDIM;
#pragma unroll
        for (int nt = 0; nt < 4; ++nt) {
            int n = wn * 32 + nt * 8 + 2 * tg;
            *reinterpret_cast<__half2*>(H0 + n) = __floats2half2_rn(
                silu(acc1[mt][nt][0]) * acc3[mt][nt][0],
                silu(acc1[mt][nt][1]) * acc3[mt][nt][1]);
            *reinterpret_cast<__half2*>(H8 + n) = __floats2half2_rn(
                silu(acc1[mt][nt][2]) * acc3[mt][nt][2],
                silu(acc1[mt][nt][3]) * acc3[mt][nt][3]);
        }
    }
}

// ---------------- GEMM2 (fp16): Y = H @ W2^T ---------------------------------
__global__ __launch_bounds__(512, 1) void gemm2_kernel(const __half* __restrict__ w2h) {
    const int e = blockIdx.z, m0 = blockIdx.x * BM, n0 = blockIdx.y * BN;
    if (m0 >= g_count[e]) return;

    extern __shared__ __align__(128) char sm[];
    const uint32_t sbase = smem_u32(sm);
    const int tid = threadIdx.x, wid = tid >> 5, lane = tid & 31;
    const int wm = wid >> 2, wn = wid & 3;
    const int grp = lane >> 2, tg = lane & 3;

    const int r = tid >> 2, h = tid & 3;
    const __half* asrc = g_Hh + ((size_t)(e * CAP + m0 + r)) * FDIM + h * 8;
    const __half* bsrc = w2h + ((size_t)e * DDIM + n0 + r) * FDIM + h * 8;
    const uint32_t doff = (uint32_t)(r * RHB + h * 16);

    auto load_stage = [&](int s, int k0) {
        uint32_t ad = sbase + (uint32_t)s * TB + doff;
        uint32_t bd = ad + STAGES * TB;
        cp16(ad, asrc + k0, 16u);
        cp16(bd, bsrc + k0, 16u);
        cp_commit();
    };

    float acc[2][4][4] = {};
    load_stage(0, 0);
    load_stage(1, BK);
    load_stage(2, 2 * BK);

    const uint32_t a_lo = (uint32_t)((lane & 15) * RHB + ((lane >> 4) << 4));
    const uint32_t b_lo = (uint32_t)((lane & 7) * RHB + (((lane >> 3) & 1) << 4)
                                     + ((lane >> 4) * 8 * RHB));

    constexpr int KT = FDIM / BK;  // 64
    for (int kt = 0; kt < KT; ++kt) {
        cp_wait<2>();
        __syncthreads();
        if (kt + 3 < KT) load_stage((kt + 3) % STAGES, (kt + 3) * BK);
        const uint32_t A_ = sbase + (uint32_t)(kt % STAGES) * TB;
        const uint32_t B_ = A_ + STAGES * TB;
#pragma unroll
        for (int ks = 0; ks < 2; ++ks) {
            const uint32_t ko = ks * 32;
            uint32_t a[2][4];
#pragma unroll
            for (int mt = 0; mt < 2; ++mt)
                ldsm4(a[mt], A_ + (uint32_t)((wm * 32 + mt * 16) * RHB) + ko + a_lo);
            uint32_t bf[2][4];
#pragma unroll
            for (int np = 0; np < 2; ++np)
                ldsm4(bf[np], B_ + (uint32_t)((wn * 32 + np * 16) * RHB) + ko + b_lo);
#pragma unroll
            for (int mt = 0; mt < 2; ++mt)
#pragma unroll
                for (int np = 0; np < 2; ++np) {
                    mma16(acc[mt][np * 2],     a[mt], bf[np][0], bf[np][1]);
                    mma16(acc[mt][np * 2 + 1], a[mt], bf[np][2], bf[np][3]);
                }
        }
    }

#pragma unroll
    for (int mt = 0; mt < 2; ++mt) {
        int mg = m0 + wm * 32 + mt * 16 + grp;
        float* Y0 = g_Y + (size_t)(e * CAP + mg) * DDIM + n0;
        float* Y8 = Y0 + 8 * DDIM;
#pragma unroll
        for (int nt = 0; nt < 4; ++nt) {
            int n = wn * 32 + nt * 8 + 2 * tg;
            Y0[n]     = acc[mt][nt][0];
            Y0[n + 1] = acc[mt][nt][1];
            Y8[n]     = acc[mt][nt][2];
            Y8[n + 1] = acc[mt][nt][3];
        }
    }
}

// ---------------- combine ----------------
__global__ __launch_bounds__(256) void combine_kernel(float* __restrict__ out) {
    int t = blockIdx.x, tid = threadIdx.x;
    float4 acc = make_float4(0.f, 0.f, 0.f, 0.f);
#pragma unroll
    for (int j = 0; j < 2; ++j) {
        int a = 2 * t + j;
        int pos = g_assign_pos[a];
        if (pos < CAP) {
            int e = g_assign_e[a];
            float g = g_assign_gate[a];
            float4 v = reinterpret_cast<const float4*>(
                g_Y + ((size_t)(e * CAP + pos)) * DDIM)[tid];
            acc.x += g * v.x; acc.y += g * v.y; acc.z += g * v.z; acc.w += g * v.w;
        }
    }
    reinterpret_cast<float4*>(out)[(size_t)t * 256 + tid] = acc;
    if (t == 0 && tid == 0) out[(size_t)TOKENS * DDIM] = g_aux;
}

// ---------------- host launcher ----------------
extern "C" void kernel_launch(void* const* d_in, const int* in_sizes, int n_in,
                              void* d_out, int out_size) {
    const float* x  = (const float*)d_in[0];
    const float* rw = (const float*)d_in[1];
    const float* rb = (const float*)d_in[2];
    const float* w1 = (const float*)d_in[3];
    const float* w3 = (const float*)d_in[4];
    const float* w2 = (const float*)d_in[5];
    float* out = (float*)d_out;

    __half* xh;  cudaGetSymbolAddress((void**)&xh,  g_xh);
    __half* w1h; cudaGetSymbolAddress((void**)&w1h, g_w1h);
    __half* w3h; cudaGetSymbolAddress((void**)&w3h, g_w3h);
    __half* w2h; cudaGetSymbolAddress((void**)&w2h, g_w2h);

    cudaFuncSetAttribute(gemm1_kernel, cudaFuncAttributeMaxDynamicSharedMemorySize, SMEM1);
    cudaFuncSetAttribute(gemm2_kernel, cudaFuncAttributeMaxDynamicSharedMemorySize, SMEM2);

    router_kernel<<<TOKENS / 8, 256>>>(x, rw, rb, xh);                        // 0
    rank_kernel<<<1, 1024>>>();                                               // 1
    tohalf3_kernel<<<4096, 256>>>(w1, w1h, w3, w3h, w2, w2h,
                                  EEXP * FDIM * DDIM / 4);                    // 2
    gemm1_kernel<<<dim3(CAP / BM, FDIM / BN, EEXP), 512, SMEM1>>>(xh, w1h, w3h); // 3 <- ncu
    gemm2_kernel<<<dim3(CAP / BM, DDIM / BN, EEXP), 512, SMEM2>>>(w2h);       // 4
    combine_kernel<<<TOKENS, 256>>>(out);                                     // 5
}

// round 12
// speedup vs baseline: 1.0513x; 1.0513x over previous
#include <cuda_runtime.h>
#include <cuda_fp16.h>
#include <cstdint>

#define DI __device__ __forceinline__

// ---------------- problem constants ----------------
constexpr int TOKENS = 4 * 2048;        // 8192
constexpr int DDIM   = 1024;
constexpr int FDIM   = 2048;
constexpr int EEXP   = 8;
constexpr int NA     = TOKENS * 2;      // 16384 assignments (K=2)
constexpr int CAP    = 2560;            // ceil(1.25 * 16384 / 8)

// ---------------- scratch (device globals; no runtime alloc) ----------------
__device__ __half g_Hh[(size_t)EEXP * CAP * FDIM];    // 80 MB (fp16 H)
__device__ float  g_Y [(size_t)EEXP * CAP * DDIM];    // 80 MB
__device__ __half g_xh [(size_t)TOKENS * DDIM];       // 16 MB
__device__ __half g_w1h[(size_t)EEXP * FDIM * DDIM];  // 32 MB
__device__ __half g_w3h[(size_t)EEXP * FDIM * DDIM];  // 32 MB
__device__ __half g_w2h[(size_t)EEXP * DDIM * FDIM];  // 32 MB
__device__ int   g_slot_token[EEXP * CAP];
__device__ int   g_count[EEXP];
__device__ int   g_assign_e[NA];
__device__ int   g_assign_pos[NA];
__device__ float g_assign_gate[NA];
__device__ float g_block_imp[(TOKENS / 8) * EEXP];
__device__ float g_aux;

// ---------------- helpers ----------------
DI uint32_t smem_u32(const void* p) {
    uint32_t a;
    asm("{ .reg .u64 t; cvta.to.shared.u64 t, %1; cvt.u32.u64 %0, t; }" : "=r"(a) : "l"(p));
    return a;
}
DI void cp16(uint32_t dst, const void* src, uint32_t valid) {
    asm volatile("cp.async.cg.shared.global [%0], [%1], 16, %2;"
                 :: "r"(dst), "l"(src), "r"(valid) : "memory");
}
DI void cp_commit() { asm volatile("cp.async.commit_group;" ::: "memory"); }
template <int N> DI void cp_wait() { asm volatile("cp.async.wait_group %0;" :: "n"(N) : "memory"); }

DI void ldsm4(uint32_t r[4], uint32_t addr) {
    asm volatile("ldmatrix.sync.aligned.m8n8.x4.shared.b16 {%0,%1,%2,%3}, [%4];"
                 : "=r"(r[0]), "=r"(r[1]), "=r"(r[2]), "=r"(r[3]) : "r"(addr));
}
// m16n8k16 fp16 mma, fp32 accum (portable sm_80+)
DI void mma16(float c[4], const uint32_t a[4], const uint32_t b0, const uint32_t b1) {
    asm volatile("mma.sync.aligned.m16n8k16.row.col.f32.f16.f16.f32 "
                 "{%0,%1,%2,%3}, {%4,%5,%6,%7}, {%8,%9}, {%0,%1,%2,%3};"
                 : "+f"(c[0]), "+f"(c[1]), "+f"(c[2]), "+f"(c[3])
                 : "r"(a[0]), "r"(a[1]), "r"(a[2]), "r"(a[3]), "r"(b0), "r"(b1));
}
DI float silu(float a) { return a / (1.f + __expf(-a)); }

// ---------------- GEMM tiling ----------------
// 256 threads/CTA, warp grid 2x4, warp tile 32x32, BM=64 -> 128 regs, 2 CTAs/SM
constexpr int BM = 64, BN = 128, BK = 32, STAGES = 4;
constexpr int RHB = 80;                       // padded row stride in bytes (32 halves + 8 pad)
constexpr int TBA = 64 * RHB;                 // 5120 B  A stage tile (64 rows)
constexpr int TBB = 128 * RHB;                // 10240 B B stage tile (128 rows)
constexpr uint32_t S_B1o = STAGES * TBA;            // 20480
constexpr uint32_t S_B3o = S_B1o + STAGES * TBB;    // 61440
constexpr uint32_t SMEM1 = S_B3o + STAGES * TBB;    // 102400 B  (2 CTAs = 204800)
constexpr uint32_t SMEM2 = S_B1o + STAGES * TBB;    //  61440 B  (2 CTAs = 122880)

// ---------------- fused fp32 -> fp16(RN) conversion of w1, w3, w2 -----------
__global__ void tohalf3_kernel(const float* __restrict__ s1, __half* __restrict__ d1,
                               const float* __restrict__ s2, __half* __restrict__ d2,
                               const float* __restrict__ s3, __half* __restrict__ d3,
                               int n4each) {
    int i = blockIdx.x * blockDim.x + threadIdx.x;
    int stride = gridDim.x * blockDim.x;
    for (int idx = i; idx < 3 * n4each; idx += stride) {
        int seg = idx / n4each, off = idx - seg * n4each;
        const float4* src = reinterpret_cast<const float4*>(seg == 0 ? s1 : (seg == 1 ? s2 : s3));
        uint2* dst = reinterpret_cast<uint2*>(seg == 0 ? d1 : (seg == 1 ? d2 : d3));
        float4 v = src[off];
        __half2 h01 = __floats2half2_rn(v.x, v.y);
        __half2 h23 = __floats2half2_rn(v.z, v.w);
        uint2 pk;
        pk.x = *reinterpret_cast<uint32_t*>(&h01);
        pk.y = *reinterpret_cast<uint32_t*>(&h23);
        dst[off] = pk;
    }
}

// ---------------- router (also emits xh = fp16(x)) ----------------
__global__ __launch_bounds__(256) void router_kernel(
    const float* __restrict__ x, const float* __restrict__ rw, const float* __restrict__ rb,
    __half* __restrict__ xh) {
    __shared__ float s_w[EEXP * DDIM];
    __shared__ float s_b[EEXP];
    __shared__ float s_probs[8][EEXP];
    int tid = threadIdx.x;
    for (int i = tid; i < EEXP * DDIM / 4; i += 256)
        reinterpret_cast<float4*>(s_w)[i] = reinterpret_cast<const float4*>(rw)[i];
    if (tid < EEXP) s_b[tid] = rb[tid];
    __syncthreads();

    int warp = tid >> 5, lane = tid & 31;
    int token = blockIdx.x * 8 + warp;
    const float4* xr = reinterpret_cast<const float4*>(x + (size_t)token * DDIM);
    uint2* xhw = reinterpret_cast<uint2*>(xh + (size_t)token * DDIM);

    float p[EEXP];
#pragma unroll
    for (int e = 0; e < EEXP; ++e) p[e] = 0.f;
#pragma unroll
    for (int j = 0; j < 8; ++j) {
        float4 v = xr[lane + j * 32];
        int base = (lane + j * 32) * 4;
#pragma unroll
        for (int e = 0; e < EEXP; ++e) {
            const float* wr = s_w + e * DDIM + base;
            p[e] += v.x * wr[0] + v.y * wr[1] + v.z * wr[2] + v.w * wr[3];
        }
        __half2 h01 = __floats2half2_rn(v.x, v.y);
        __half2 h23 = __floats2half2_rn(v.z, v.w);
        uint2 pk;
        pk.x = *reinterpret_cast<uint32_t*>(&h01);
        pk.y = *reinterpret_cast<uint32_t*>(&h23);
        xhw[lane + j * 32] = pk;
    }
#pragma unroll
    for (int off = 16; off > 0; off >>= 1)
#pragma unroll
        for (int e = 0; e < EEXP; ++e) p[e] += __shfl_xor_sync(0xffffffffu, p[e], off);

    if (lane == 0) {
        float pr[EEXP];
        float mx = -1e30f;
#pragma unroll
        for (int e = 0; e < EEXP; ++e) { p[e] += s_b[e]; mx = fmaxf(mx, p[e]); }
        float sum = 0.f;
#pragma unroll
        for (int e = 0; e < EEXP; ++e) { pr[e] = expf(p[e] - mx); sum += pr[e]; }
        float inv = 1.f / sum;
#pragma unroll
        for (int e = 0; e < EEXP; ++e) pr[e] *= inv;

        int e0 = 0;
#pragma unroll
        for (int e = 1; e < EEXP; ++e) if (pr[e] > pr[e0]) e0 = e;
        int e1 = (e0 == 0) ? 1 : 0;
#pragma unroll
        for (int e = 0; e < EEXP; ++e) if (e != e0 && pr[e] > pr[e1]) e1 = e;

        float s2 = fmaxf(pr[e0] + pr[e1], 1e-9f);
        g_assign_e[2 * token]        = e0;
        g_assign_gate[2 * token]     = pr[e0] / s2;
        g_assign_e[2 * token + 1]    = e1;
        g_assign_gate[2 * token + 1] = pr[e1] / s2;
#pragma unroll
        for (int e = 0; e < EEXP; ++e) s_probs[warp][e] = pr[e];
    }
    __syncthreads();
    if (tid < EEXP) {
        float s = 0.f;
#pragma unroll
        for (int w = 0; w < 8; ++w) s += s_probs[w][tid];
        g_block_imp[blockIdx.x * EEXP + tid] = s;
    }
}

// ---------------- rank: init slots + stable per-expert ranking + aux ---------
__global__ __launch_bounds__(1024) void rank_kernel() {
    __shared__ int warp_off[32][EEXP];
    __shared__ int base[EEXP];
    __shared__ float imp_part[1024];
    __shared__ float prod[EEXP];
    int tid = threadIdx.x, warp = tid >> 5, lane = tid & 31;
    for (int i = tid; i < EEXP * CAP; i += 1024) g_slot_token[i] = -1;
    if (tid < EEXP) base[tid] = 0;
    __syncthreads();

    for (int chunk = 0; chunk < NA / 1024; ++chunk) {
        int a = chunk * 1024 + tid;
        int e = g_assign_e[a];
        unsigned m = __match_any_sync(0xffffffffu, e);
        int rank = __popc(m & ((1u << lane) - 1));
        int cnt  = __popc(m);
        int leader = __ffs(m) - 1;
        if (tid < 256) reinterpret_cast<int*>(warp_off)[tid] = 0;
        __syncthreads();
        if (lane == leader) warp_off[warp][e] = cnt;
        __syncthreads();
        if (tid < EEXP) {
            int run = base[tid];
            for (int w = 0; w < 32; ++w) { int c = warp_off[w][tid]; warp_off[w][tid] = run; run += c; }
            base[tid] = run;
        }
        __syncthreads();
        int pos = warp_off[warp][e] + rank;
        g_assign_pos[a] = pos;
        if (pos < CAP) g_slot_token[e * CAP + pos] = a >> 1;
        __syncthreads();
    }

    float s = 0.f;
    int eidx = tid & 7;
    for (int b = tid >> 3; b < TOKENS / 8; b += 128) s += g_block_imp[b * EEXP + eidx];
    imp_part[tid] = s;
    __syncthreads();
    if (tid < EEXP) {
        float tot = 0.f;
        for (int i = tid; i < 1024; i += 8) tot += imp_part[i];
        float imp = tot / (float)TOKENS;
        float ld  = (float)base[tid] / (float)NA;
        prod[tid] = imp * ld;
        g_count[tid] = base[tid];
    }
    __syncthreads();
    if (tid == 0) {
        float acc = 0.f;
        for (int e = 0; e < EEXP; ++e) acc += prod[e];
        g_aux = 0.01f * (float)EEXP * acc;
    }
}

// ---------------- GEMM1 (fp16): H = silu(Xb@W1^T) * (Xb@W3^T) ----------------
__global__ __launch_bounds__(256, 2) void gemm1_kernel(
    const __half* __restrict__ xh, const __half* __restrict__ w1h, const __half* __restrict__ w3h) {
    const int e = blockIdx.z, m0 = blockIdx.x * BM, n0 = blockIdx.y * BN;
    if (m0 >= g_count[e]) return;           // outputs for these slots are never read

    extern __shared__ __align__(128) char sm[];
    const uint32_t sbase = smem_u32(sm);
    const int tid = threadIdx.x, wid = tid >> 5, lane = tid & 31;
    const int wm = wid >> 2, wn = wid & 3;  // warp grid 2x4 -> warp tile 32x32
    const int grp = lane >> 2, tg = lane & 3;

    // loader: 4 threads per row of 64; A 1x cp16, B1/B3 2x cp16 (rows r and r+64)
    const int r = tid >> 2, h = tid & 3;
    const int tok = g_slot_token[e * CAP + m0 + r];
    const __half* asrc = xh + (size_t)(tok < 0 ? 0 : tok) * DDIM + h * 8;
    const uint32_t av = (tok >= 0) ? 16u : 0u;
    const __half* b1src  = w1h + ((size_t)e * FDIM + n0 + r) * DDIM + h * 8;
    const __half* b3src  = w3h + ((size_t)e * FDIM + n0 + r) * DDIM + h * 8;
    const uint32_t dro = (uint32_t)(r * RHB + h * 16);

    auto load_stage = [&](int s, int k0) {
        uint32_t ad  = sbase + (uint32_t)s * TBA + dro;
        uint32_t b1d = sbase + S_B1o + (uint32_t)s * TBB + dro;
        uint32_t b3d = sbase + S_B3o + (uint32_t)s * TBB + dro;
        cp16(ad, asrc + k0, av);
        cp16(b1d,                 b1src + k0,                    16u);
        cp16(b1d + 64u * RHB,     b1src + k0 + (size_t)64 * DDIM, 16u);
        cp16(b3d,                 b3src + k0,                    16u);
        cp16(b3d + 64u * RHB,     b3src + k0 + (size_t)64 * DDIM, 16u);
        cp_commit();
    };

    float acc1[2][4][4] = {}, acc3[2][4][4] = {};
    load_stage(0, 0);
    load_stage(1, BK);
    load_stage(2, 2 * BK);

    // ldmatrix lane offsets
    const uint32_t a_lo = (uint32_t)((lane & 15) * RHB + ((lane >> 4) << 4));
    const uint32_t b_lo = (uint32_t)((lane & 7) * RHB + (((lane >> 3) & 1) << 4)
                                     + ((lane >> 4) * 8 * RHB));

    constexpr int KT = DDIM / BK;  // 32
    for (int kt = 0; kt < KT; ++kt) {
        cp_wait<2>();
        __syncthreads();
        if (kt + 3 < KT) load_stage((kt + 3) % STAGES, (kt + 3) * BK);
        const uint32_t A_  = sbase + (uint32_t)(kt % STAGES) * TBA;
        const uint32_t B1_ = sbase + S_B1o + (uint32_t)(kt % STAGES) * TBB;
        const uint32_t B3_ = sbase + S_B3o + (uint32_t)(kt % STAGES) * TBB;
#pragma unroll
        for (int ks = 0; ks < 2; ++ks) {
            const uint32_t ko = ks * 32;
            uint32_t a[2][4];
#pragma unroll
            for (int mt = 0; mt < 2; ++mt)
                ldsm4(a[mt], A_ + (uint32_t)((wm * 32 + mt * 16) * RHB) + ko + a_lo);
            uint32_t b1f[2][4], b3f[2][4];
#pragma unroll
            for (int np = 0; np < 2; ++np) {
                uint32_t nrow = (uint32_t)((wn * 32 + np * 16) * RHB) + ko + b_lo;
                ldsm4(b1f[np], B1_ + nrow);
                ldsm4(b3f[np], B3_ + nrow);
            }
#pragma unroll
            for (int mt = 0; mt < 2; ++mt)
#pragma unroll
                for (int np = 0; np < 2; ++np) {
                    mma16(acc1[mt][np * 2],     a[mt], b1f[np][0], b1f[np][1]);
                    mma16(acc1[mt][np * 2 + 1], a[mt], b1f[np][2], b1f[np][3]);
                    mma16(acc3[mt][np * 2],     a[mt], b3f[np][0], b3f[np][1]);
                    mma16(acc3[mt][np * 2 + 1], a[mt], b3f[np][2], b3f[np][3]);
                }
        }
    }

    // epilogue: silu(h1)*h3 -> g_Hh (fp16; it is gemm2's A operand)
#pragma unroll
    for (int mt = 0; mt < 2; ++mt) {
        int mg = m0 + wm * 32 + mt * 16 + grp;
        __half* H0 = g_Hh + (size_t)(e * CAP + mg) * FDIM + n0;
        __half* H8 = H0 + 8 * FDIM;
#pragma unroll
        for (int nt = 0; nt < 4; ++nt) {
            int n = wn * 32 + nt * 8 + 2 * tg;
            *reinterpret_cast<__half2*>(H0 + n) = __floats2half2_rn(
                silu(acc1[mt][nt][0]) * acc3[mt][nt][0],
                silu(acc1[mt][nt][1]) * acc3[mt][nt][1]);
            *reinterpret_cast<__half2*>(H8 + n) = __floats2half2_rn(
                silu(acc1[mt][nt][2]) * acc3[mt][nt][2],
                silu(acc1[mt][nt][3]) * acc3[mt][nt][3]);
        }
    }
}

// ---------------- GEMM2 (fp16): Y = H @ W2^T ---------------------------------
__global__ __launch_bounds__(256, 2) void gemm2_kernel(const __half* __restrict__ w2h) {
    const int e = blockIdx.z, m0 = blockIdx.x * BM, n0 = blockIdx.y * BN;
    if (m0 >= g_count[e]) return;

    extern __shared__ __align__(128) char sm[];
    const uint32_t sbase = smem_u32(sm);
    const int tid = threadIdx.x, wid = tid >> 5, lane = tid & 31;
    const int wm = wid >> 2, wn = wid & 3;
    const int grp = lane >> 2, tg = lane & 3;

    const int r = tid >> 2, h = tid & 3;
    const __half* asrc = g_Hh + ((size_t)(e * CAP + m0 + r)) * FDIM + h * 8;
    const __half* bsrc = w2h + ((size_t)e * DDIM + n0 + r) * FDIM + h * 8;
    const uint32_t dro = (uint32_t)(r * RHB + h * 16);

    auto load_stage = [&](int s, int k0) {
        uint32_t ad = sbase + (uint32_t)s * TBA + dro;
        uint32_t bd = sbase + S_B1o + (uint32_t)s * TBB + dro;
        cp16(ad, asrc + k0, 16u);
        cp16(bd,             bsrc + k0,                     16u);
        cp16(bd + 64u * RHB, bsrc + k0 + (size_t)64 * FDIM, 16u);
        cp_commit();
    };

    float acc[2][4][4] = {};
    load_stage(0, 0);
    load_stage(1, BK);
    load_stage(2, 2 * BK);

    const uint32_t a_lo = (uint32_t)((lane & 15) * RHB + ((lane >> 4) << 4));
    const uint32_t b_lo = (uint32_t)((lane & 7) * RHB + (((lane >> 3) & 1) << 4)
                                     + ((lane >> 4) * 8 * RHB));

    constexpr int KT = FDIM / BK;  // 64
    for (int kt = 0; kt < KT; ++kt) {
        cp_wait<2>();
        __syncthreads();
        if (kt + 3 < KT) load_stage((kt + 3) % STAGES, (kt + 3) * BK);
        const uint32_t A_ = sbase + (uint32_t)(kt % STAGES) * TBA;
        const uint32_t B_ = sbase + S_B1o + (uint32_t)(kt % STAGES) * TBB;
#pragma unroll
        for (int ks = 0; ks < 2; ++ks) {
            const uint32_t ko = ks * 32;
            uint32_t a[2][4];
#pragma unroll
            for (int mt = 0; mt < 2; ++mt)
                ldsm4(a[mt], A_ + (uint32_t)((wm * 32 + mt * 16) * RHB) + ko + a_lo);
            uint32_t bf[2][4];
#pragma unroll
            for (int np = 0; np < 2; ++np)
                ldsm4(bf[np], B_ + (uint32_t)((wn * 32 + np * 16) * RHB) + ko + b_lo);
#pragma unroll
            for (int mt = 0; mt < 2; ++mt)
#pragma unroll
                for (int np = 0; np < 2; ++np) {
                    mma16(acc[mt][np * 2],     a[mt], bf[np][0], bf[np][1]);
                    mma16(acc[mt][np * 2 + 1], a[mt], bf[np][2], bf[np][3]);
                }
        }
    }

#pragma unroll
    for (int mt = 0; mt < 2; ++mt) {
        int mg = m0 + wm * 32 + mt * 16 + grp;
        float* Y0 = g_Y + (size_t)(e * CAP + mg) * DDIM + n0;
        float* Y8 = Y0 + 8 * DDIM;
#pragma unroll
        for (int nt = 0; nt < 4; ++nt) {
            int n = wn * 32 + nt * 8 + 2 * tg;
            Y0[n]     = acc[mt][nt][0];
            Y0[n + 1] = acc[mt][nt][1];
            Y8[n]     = acc[mt][nt][2];
            Y8[n + 1] = acc[mt][nt][3];
        }
    }
}

// ---------------- combine ----------------
__global__ __launch_bounds__(256) void combine_kernel(float* __restrict__ out) {
    int t = blockIdx.x, tid = threadIdx.x;
    float4 acc = make_float4(0.f, 0.f, 0.f, 0.f);
#pragma unroll
    for (int j = 0; j < 2; ++j) {
        int a = 2 * t + j;
        int pos = g_assign_pos[a];
        if (pos < CAP) {
            int e = g_assign_e[a];
            float g = g_assign_gate[a];
            float4 v = reinterpret_cast<const float4*>(
                g_Y + ((size_t)(e * CAP + pos)) * DDIM)[tid];
            acc.x += g * v.x; acc.y += g * v.y; acc.z += g * v.z; acc.w += g * v.w;
        }
    }
    reinterpret_cast<float4*>(out)[(size_t)t * 256 + tid] = acc;
    if (t == 0 && tid == 0) out[(size_t)TOKENS * DDIM] = g_aux;
}

// ---------------- host launcher ----------------
extern "C" void kernel_launch(void* const* d_in, const int* in_sizes, int n_in,
                              void* d_out, int out_size) {
    const float* x  = (const float*)d_in[0];
    const float* rw = (const float*)d_in[1];
    const float* rb = (const float*)d_in[2];
    const float* w1 = (const float*)d_in[3];
    const float* w3 = (const float*)d_in[4];
    const float* w2 = (const float*)d_in[5];
    float* out = (float*)d_out;

    __half* xh;  cudaGetSymbolAddress((void**)&xh,  g_xh);
    __half* w1h; cudaGetSymbolAddress((void**)&w1h, g_w1h);
    __half* w3h; cudaGetSymbolAddress((void**)&w3h, g_w3h);
    __half* w2h; cudaGetSymbolAddress((void**)&w2h, g_w2h);

    cudaFuncSetAttribute(gemm1_kernel, cudaFuncAttributeMaxDynamicSharedMemorySize, SMEM1);
    cudaFuncSetAttribute(gemm2_kernel, cudaFuncAttributeMaxDynamicSharedMemorySize, SMEM2);

    router_kernel<<<TOKENS / 8, 256>>>(x, rw, rb, xh);                        // 0
    rank_kernel<<<1, 1024>>>();                                               // 1
    tohalf3_kernel<<<4096, 256>>>(w1, w1h, w3, w3h, w2, w2h,
                                  EEXP * FDIM * DDIM / 4);                    // 2
    gemm1_kernel<<<dim3(CAP / BM, FDIM / BN, EEXP), 256, SMEM1>>>(xh, w1h, w3h); // 3 <- ncu
    gemm2_kernel<<<dim3(CAP / BM, DDIM / BN, EEXP), 256, SMEM2>>>(w2h);       // 4
    combine_kernel<<<TOKENS, 256>>>(out);                                     // 5
}